// round 12
// baseline (speedup 1.0000x reference)
#include <cuda_runtime.h>

#define NTOK 20
#define NB   4
#define NI   80          // instances/row: [b0|b1|b2|b3] x 20 tokens, 320B rows
#define TPB  128
#define MAXCTAS 8192

typedef unsigned long long ull;

// per-CTA global staging: S1=150 rows (tb/ath/hpH), S2=100 (m2h/fold-scratch), S3=50 (h2)
#define S1_ROWS 150
#define S2_ROWS 100
#define S3_ROWS 50
#define SLOT_FLOATS ((S1_ROWS + S2_ROWS + S3_ROWS) * NI)
__device__ __align__(16) float g_scr[(size_t)MAXCTAS * SLOT_FLOATS];

// ---------- packed f32x2 helpers ----------
__device__ __forceinline__ ull pk2(float lo, float hi) {
    ull r;
    asm("mov.b64 %0, {%1,%2};" : "=l"(r)
        : "r"(__float_as_uint(lo)), "r"(__float_as_uint(hi)));
    return r;
}
__device__ __forceinline__ void upk2(ull v, float& lo, float& hi) {
    unsigned int a, b;
    asm("mov.b64 {%0,%1}, %2;" : "=r"(a), "=r"(b) : "l"(v));
    lo = __uint_as_float(a); hi = __uint_as_float(b);
}
__device__ __forceinline__ void fma2(ull& d, ull a, ull b) {
    asm("fma.rn.f32x2 %0, %1, %2, %0;" : "+l"(d) : "l"(a), "l"(b));
}

// ---------- dense over 4 blocked batches ----------
// rows [F][NI]; pairs never straddle batches (batch len 20 even, pairs 8B-aligned).
// Thread u: q=u/TGN owns JT neurons, tg=u%TGN owns TT contiguous instances.
// FOLDB: bias from foldf[FO][4] selected per-pair by batch; else scalar bias Bv[FO].
template<int FI, int FO, int WS, int JT, int TT, bool RELU, bool FOLDB>
__device__ __forceinline__ void dense(const float* __restrict__ W,
                                      const float* __restrict__ Bv,
                                      const float* __restrict__ in,
                                      float* __restrict__ outp) {
    constexpr int TGN = NI / TT;
    constexpr int NP  = TT / 2;
    constexpr int NL  = TT / 4;
    constexpr int U   = (FO / JT) * TGN;
    static_assert(FO % JT == 0, "JT");
    const int tid = threadIdx.x;
    for (int u = tid; u < U; u += TPB) {
        const int q  = u / TGN;
        const int tg = u % TGN;
        const int j0 = q * JT;
        ull acc[JT][NP];
        #pragma unroll
        for (int j = 0; j < JT; j++) {
            if constexpr (FOLDB) {
                #pragma unroll
                for (int p = 0; p < NP; p++) {
                    const int bi = (TT * tg + 2 * p) / NTOK;
                    const float f = Bv[(j0 + j) * 4 + bi];
                    acc[j][p] = pk2(f, f);
                }
            } else {
                const float b = Bv[j0 + j];
                const ull bb = pk2(b, b);
                #pragma unroll
                for (int p = 0; p < NP; p++) acc[j][p] = bb;
            }
        }
        const float* wp = W + j0;
        const float* ip = in + TT * tg;
        #pragma unroll 2
        for (int i = 0; i < FI; i++) {
            ulonglong2 v[NL];
            #pragma unroll
            for (int l = 0; l < NL; l++)
                v[l] = *reinterpret_cast<const ulonglong2*>(ip + i * NI + 4 * l);
            float w[JT];
            if constexpr (JT == 4) {
                const float4 wv = *reinterpret_cast<const float4*>(wp + i * WS);
                w[0] = wv.x; w[1] = wv.y; w[2] = wv.z; w[3] = wv.w;
            } else {
                #pragma unroll
                for (int jj = 0; jj < JT / 2; jj++) {
                    const float2 wv =
                        *reinterpret_cast<const float2*>(wp + i * WS + 2 * jj);
                    w[2 * jj] = wv.x; w[2 * jj + 1] = wv.y;
                }
            }
            #pragma unroll
            for (int j = 0; j < JT; j++) {
                const ull wd = pk2(w[j], w[j]);
                #pragma unroll
                for (int l = 0; l < NL; l++) {
                    fma2(acc[j][2 * l],     v[l].x, wd);
                    fma2(acc[j][2 * l + 1], v[l].y, wd);
                }
            }
        }
        #pragma unroll
        for (int j = 0; j < JT; j++) {
            if (RELU) {
                #pragma unroll
                for (int p = 0; p < NP; p++) {
                    float a, b; upk2(acc[j][p], a, b);
                    acc[j][p] = pk2(fmaxf(a, 0.f), fmaxf(b, 0.f));
                }
            }
            float* op = outp + (j0 + j) * NI + TT * tg;
            #pragma unroll
            for (int l = 0; l < NL; l++) {
                ulonglong2 s;
                s.x = acc[j][2 * l]; s.y = acc[j][2 * l + 1];
                *reinterpret_cast<ulonglong2*>(op + 4 * l) = s;
            }
        }
    }
}

// ---------- fused: out1 = relu(W1.in + b1), out2 = relu(W2.in + foldf) ----------
// TT=8 (2 passes): shares activation LDS between both matrices.
__device__ __forceinline__ void dense_fused100(const float* __restrict__ W1,
        const float* __restrict__ Bv1, const float* __restrict__ W2,
        const float* __restrict__ foldf, const float* __restrict__ in_sh,
        float* __restrict__ out1, float* __restrict__ out2) {
    constexpr int U = 25 * 10;
    const int tid = threadIdx.x;
    for (int u = tid; u < U; u += TPB) {
        const int q = u / 10, tg = u % 10, j0 = 4 * q;
        ull a1[4][4], a2[4][4];
        #pragma unroll
        for (int j = 0; j < 4; j++) {
            const float b = Bv1[j0 + j];
            const ull bb = pk2(b, b);
            #pragma unroll
            for (int p = 0; p < 4; p++) a1[j][p] = bb;
            #pragma unroll
            for (int p = 0; p < 4; p++) {
                const int bi = (8 * tg + 2 * p) / NTOK;
                const float f = foldf[(j0 + j) * 4 + bi];
                a2[j][p] = pk2(f, f);
            }
        }
        const float* ip = in_sh + 8 * tg;
        #pragma unroll 2
        for (int i = 0; i < 100; i++) {
            const ulonglong2 v0 = *reinterpret_cast<const ulonglong2*>(ip + i * NI);
            const ulonglong2 v1 = *reinterpret_cast<const ulonglong2*>(ip + i * NI + 4);
            const float4 w1 = *reinterpret_cast<const float4*>(W1 + i * 100 + j0);
            const float4 w2 = *reinterpret_cast<const float4*>(W2 + i * 100 + j0);
            const float wa1[4] = {w1.x, w1.y, w1.z, w1.w};
            const float wa2[4] = {w2.x, w2.y, w2.z, w2.w};
            #pragma unroll
            for (int j = 0; j < 4; j++) {
                ull d = pk2(wa1[j], wa1[j]);
                fma2(a1[j][0], v0.x, d); fma2(a1[j][1], v0.y, d);
                fma2(a1[j][2], v1.x, d); fma2(a1[j][3], v1.y, d);
                d = pk2(wa2[j], wa2[j]);
                fma2(a2[j][0], v0.x, d); fma2(a2[j][1], v0.y, d);
                fma2(a2[j][2], v1.x, d); fma2(a2[j][3], v1.y, d);
            }
        }
        #pragma unroll
        for (int j = 0; j < 4; j++) {
            #pragma unroll
            for (int p = 0; p < 4; p++) {
                float a, b;
                upk2(a1[j][p], a, b);
                a1[j][p] = pk2(fmaxf(a, 0.f), fmaxf(b, 0.f));
                upk2(a2[j][p], a, b);
                a2[j][p] = pk2(fmaxf(a, 0.f), fmaxf(b, 0.f));
            }
            float* o1 = out1 + (j0 + j) * NI + 8 * tg;
            float* o2 = out2 + (j0 + j) * NI + 8 * tg;
            ulonglong2 s;
            s.x = a1[j][0]; s.y = a1[j][1]; *reinterpret_cast<ulonglong2*>(o1) = s;
            s.x = a1[j][2]; s.y = a1[j][3]; *reinterpret_cast<ulonglong2*>(o1 + 4) = s;
            s.x = a2[j][0]; s.y = a2[j][1]; *reinterpret_cast<ulonglong2*>(o2) = s;
            s.x = a2[j][2]; s.y = a2[j][3]; *reinterpret_cast<ulonglong2*>(o2 + 4) = s;
        }
    }
}

// ---------- fold: foldf[j][bi] = b[j] + sum_i g4[i][bi] * W[(F1+i)*FO+j] ----------
// Two-stage, float4 weight LDGs; partials in global scratch. Internal syncthreads.
template<int F1, int FG, int FO>
__device__ __forceinline__ void fold_bias_v(const float* __restrict__ W,
        const float* __restrict__ Bv, const float* __restrict__ g4,
        float* __restrict__ foldf, ull* __restrict__ scratch) {
    constexpr int IC = 5, CH = FG / IC, U = (FO / 4) * IC;
    const int tid = threadIdx.x;
    for (int u = tid; u < U; u += TPB) {
        const int q = u / IC, ic = u % IC, j0 = 4 * q, i0 = ic * CH;
        ull acc[4][2] = {};
        #pragma unroll
        for (int k = 0; k < CH; k++) {
            const int i = i0 + k;
            const float4 wv = *reinterpret_cast<const float4*>(W + (F1 + i) * FO + j0);
            const ulonglong2 g = *reinterpret_cast<const ulonglong2*>(g4 + i * 4);
            const float wa[4] = {wv.x, wv.y, wv.z, wv.w};
            #pragma unroll
            for (int j = 0; j < 4; j++) {
                const ull wd = pk2(wa[j], wa[j]);
                fma2(acc[j][0], g.x, wd);
                fma2(acc[j][1], g.y, wd);
            }
        }
        #pragma unroll
        for (int j = 0; j < 4; j++) {
            scratch[u * 8 + j * 2]     = acc[j][0];
            scratch[u * 8 + j * 2 + 1] = acc[j][1];
        }
    }
    __syncthreads();
    if (tid < FO) {
        const int q = tid / 4, jj = tid % 4;
        const float b = Bv[tid];
        ull s0 = pk2(b, b), s1 = pk2(b, b);
        const ull one = pk2(1.f, 1.f);
        #pragma unroll
        for (int ic = 0; ic < IC; ic++) {
            const int uu = q * IC + ic;
            fma2(s0, scratch[uu * 8 + jj * 2],     one);
            fma2(s1, scratch[uu * 8 + jj * 2 + 1], one);
        }
        float a, bb, c, d; upk2(s0, a, bb); upk2(s1, c, d);
        foldf[tid * 4 + 0] = a; foldf[tid * 4 + 1] = bb;
        foldf[tid * 4 + 2] = c; foldf[tid * 4 + 3] = d;
    }
}

// smem layout (floats): A(100 rows, 32KB) + X(13 rows) + small vectors = ~41KB
#define OFF_A    0
#define OFF_X    (OFF_A + 100 * NI)
#define OFF_G4   (OFF_X + 13 * NI)
#define OFF_FOLD (OFF_G4 + 400)
#define OFF_WS4  (OFF_FOLD + 400)
#define OFF_MASK (OFF_WS4 + 200)
#define OFF_SE   (OFF_MASK + NI)
#define OFF_W    (OFF_SE + NI)
#define SMEM_FLOATS (OFF_W + NI)
#define SMEM_BYTES (SMEM_FLOATS * 4)

__global__ void __launch_bounds__(TPB, 5)
sp_kernel(const float* __restrict__ state,
          const float* __restrict__ m1w0, const float* __restrict__ m1b0,
          const float* __restrict__ m1w1, const float* __restrict__ m1b1,
          const float* __restrict__ m2w0, const float* __restrict__ m2b0,
          const float* __restrict__ m2w1, const float* __restrict__ m2b1,
          const float* __restrict__ atw0, const float* __restrict__ atb0,
          const float* __restrict__ atw1, const float* __restrict__ atb1,
          const float* __restrict__ atw2, const float* __restrict__ atb2,
          const float* __restrict__ hpw0, const float* __restrict__ hpb0,
          const float* __restrict__ hpw1, const float* __restrict__ hpb1,
          const float* __restrict__ hpw2, const float* __restrict__ hpb2,
          float* __restrict__ out)
{
    extern __shared__ __align__(16) float sm[];
    float* A       = sm + OFF_A;     // h1; at1 out; hp1 out
    float* X       = sm + OFF_X;     // state features
    float* g4      = sm + OFF_G4;    // [100][4] global-state per batch
    float* foldf   = sm + OFF_FOLD;  // [100][4] folded bias per batch
    float* ws4     = sm + OFF_WS4;   // [50][4]
    float* mask_sh = sm + OFF_MASK;
    float* se_sh   = sm + OFF_SE;
    float* w_sh    = sm + OFF_W;

    const int tid = threadIdx.x;
    const int b0  = NB * blockIdx.x;
    float* slot = g_scr + (size_t)blockIdx.x * SLOT_FLOATS;
    float* S1 = slot;                       // 150 rows: tb -> ath -> hpH
    float* S2 = slot + S1_ROWS * NI;        // 100 rows: fold scratch / m2h
    float* S3 = slot + (S1_ROWS + S2_ROWS) * NI;  // 50 rows: h2

    // ---- load 4 batches of state, feature-major blocked [b0|b1|b2|b3] ----
    const float* st = state + (size_t)b0 * (NTOK * 14);
    for (int t = tid; t < NB * NTOK * 14; t += TPB) {
        const int bi = t / (NTOK * 14);
        const int r  = t - bi * (NTOK * 14);
        const int n  = r / 14, d = r % 14;
        const float v = st[(size_t)bi * (NTOK * 14) + r];
        if (d == 13) mask_sh[bi * NTOK + n] = v;
        else         X[d * NI + bi * NTOK + n] = v;
    }
    __syncthreads();

    // ---- m1: 13 -> 150 (relu, to S1 global) -> 100 (relu, h1 in A) ----
    dense<13, 150, 150, 6, 8, true, false>(m1w0, m1b0, X, S1);
    __syncthreads();
    dense<150, 100, 100, 4, 16, true, false>(m1w1, m1b1, S1, A);
    __syncthreads();

    // ---- masked mean of h1 -> g4[100][4] ----
    if (tid < 100) {
        const ull* mp = reinterpret_cast<const ull*>(mask_sh);
        const ull* hp = reinterpret_cast<const ull*>(A + tid * NI);
        const ull one = pk2(1.f, 1.f);
        #pragma unroll
        for (int bi = 0; bi < NB; bi++) {
            ull macc = 0, acc = 0;
            #pragma unroll
            for (int k = 0; k < 10; k++) {
                fma2(macc, mp[bi * 10 + k], one);
                fma2(acc,  hp[bi * 10 + k], mp[bi * 10 + k]);
            }
            float a, b; upk2(macc, a, b);
            const float ms = a + b;
            upk2(acc, a, b);
            g4[tid * 4 + bi] = (ms > 0.f) ? (a + b) * (1.f / ms) : 0.f;
        }
    }
    __syncthreads();

    // ---- fold at0's global half (scratch in S2, free before m2h) ----
    fold_bias_v<100, 100, 100>(atw0, atb0, g4, foldf, reinterpret_cast<ull*>(S2));
    __syncthreads();

    // ---- FUSED: m2w0 (A -> S2 m2h) + at0 (A -> S1 ath), one read of h1 ----
    dense_fused100(m2w0, m2b0, atw0, foldf, A, S2, S1);
    __syncthreads();
    // A (h1) dead

    // ---- m2w1: S2 -> h2 in S3; at1: S1 -> A (independent, no barrier between) ----
    dense<100, 50, 50, 2, 16, false, false>(m2w1, m2b1, S2, S3);
    dense<100, 100, 100, 4, 16, true, false>(atw1, atb1, S1, A);
    __syncthreads();

    // ---- attention scores from A ----
    if (tid < NI) {
        float s = atb2[0];
        #pragma unroll 4
        for (int i = 0; i < 100; i++) s = fmaf(A[i * NI + tid], atw2[i], s);
        s *= mask_sh[tid];
        se_sh[tid] = (s != 0.f) ? expf(s) : 0.f;
    }
    __syncthreads();
    if (tid < NI) {
        const int bi = tid / NTOK;
        float ssum = 0.f;
        #pragma unroll
        for (int n = 0; n < NTOK; n++) ssum += se_sh[bi * NTOK + n];
        w_sh[tid] = (ssum > 0.f) ? se_sh[tid] / ssum : 0.f;
    }
    __syncthreads();

    // ---- weighted sum of h2 (S3) -> ws4[50][4] ----
    if (tid < 50) {
        const ull* hp = reinterpret_cast<const ull*>(S3 + tid * NI);
        const ull* wp = reinterpret_cast<const ull*>(w_sh);
        #pragma unroll
        for (int bi = 0; bi < NB; bi++) {
            ull acc = 0;
            #pragma unroll
            for (int k = 0; k < 10; k++) fma2(acc, hp[bi * 10 + k], wp[bi * 10 + k]);
            float a, b; upk2(acc, a, b);
            ws4[tid * 4 + bi] = a + b;
        }
    }
    __syncthreads();

    // ---- fold hp0's weighted-sum half (scratch in S2: m2h consumed) ----
    fold_bias_v<50, 50, 100>(hpw0, hpb0, ws4, foldf, reinterpret_cast<ull*>(S2));
    __syncthreads();

    // ---- head: hp0: S3 (h2) -> S1 (fold bias); hp1: S1 -> A ----
    dense<50, 100, 100, 4, 16, true, true>(hpw0, foldf, S3, S1);
    __syncthreads();
    dense<100, 100, 100, 4, 16, true, false>(hpw1, hpb1, S1, A);
    __syncthreads();

    // ---- final 100 -> 7 from A: unit = (batch, token-pair, neuron) = 280 ----
    for (int t = tid; t < NB * 70; t += TPB) {
        const int bi = t / 70;
        const int r  = t % 70;
        const int k  = r / 7, j = r % 7;
        ull acc = pk2(hpb2[j], hpb2[j]);
        const ull* ip = reinterpret_cast<const ull*>(A) + bi * 10 + k;
        #pragma unroll 4
        for (int i = 0; i < 100; i++) {
            const float w = hpw2[i * 7 + j];
            fma2(acc, ip[i * (NI / 2)], pk2(w, w));
        }
        float a, c; upk2(acc, a, c);
        float* ob = out + (size_t)(b0 + bi) * (NTOK * 7);
        ob[(2 * k)     * 7 + j] = a;
        ob[(2 * k + 1) * 7 + j] = c;
    }
}

extern "C" void kernel_launch(void* const* d_in, const int* in_sizes, int n_in,
                              void* d_out, int out_size) {
    cudaFuncSetAttribute(sp_kernel,
                         cudaFuncAttributeMaxDynamicSharedMemorySize, SMEM_BYTES);
    cudaFuncSetAttribute(sp_kernel,
                         cudaFuncAttributePreferredSharedMemoryCarveout, 100);

    // state is the only huge tensor (B*20*14 elems); detect its position by size.
    int si, wb;
    if (in_sizes[0] > 1000000) { si = 0;        wb = 1; }
    else                       { si = n_in - 1; wb = 0; }
    const float* state = (const float*)d_in[si];
    const int B = in_sizes[si] / (NTOK * 14);

    sp_kernel<<<B / NB, TPB, SMEM_BYTES>>>(
        state,
        (const float*)d_in[wb + 0],  (const float*)d_in[wb + 1],
        (const float*)d_in[wb + 2],  (const float*)d_in[wb + 3],
        (const float*)d_in[wb + 4],  (const float*)d_in[wb + 5],
        (const float*)d_in[wb + 6],  (const float*)d_in[wb + 7],
        (const float*)d_in[wb + 8],  (const float*)d_in[wb + 9],
        (const float*)d_in[wb + 10], (const float*)d_in[wb + 11],
        (const float*)d_in[wb + 12], (const float*)d_in[wb + 13],
        (const float*)d_in[wb + 14], (const float*)d_in[wb + 15],
        (const float*)d_in[wb + 16], (const float*)d_in[wb + 17],
        (const float*)d_in[wb + 18], (const float*)d_in[wb + 19],
        (float*)d_out);
}

// round 13
// speedup vs baseline: 1.7641x; 1.7641x over previous
#include <cuda_runtime.h>

#define NTOK 20
#define NI   40          // instances per row: [b0 tok0..19 | b1 tok0..19], 160B rows
#define TPB  128
#define MAXCTAS 16384
#define SCRATCH_STRIDE 4096   // floats per CTA (100 rows x 40, padded to 16KB)

typedef unsigned long long ull;

// global scratch for the fused stage's m2-hidden output (per-CTA slot)
__device__ __align__(16) float g_m2h[(size_t)MAXCTAS * SCRATCH_STRIDE];

// ---------- packed f32x2 helpers ----------
__device__ __forceinline__ ull pk2(float lo, float hi) {
    ull r;
    asm("mov.b64 %0, {%1,%2};" : "=l"(r)
        : "r"(__float_as_uint(lo)), "r"(__float_as_uint(hi)));
    return r;
}
__device__ __forceinline__ void upk2(ull v, float& lo, float& hi) {
    unsigned int a, b;
    asm("mov.b64 {%0,%1}, %2;" : "=r"(a), "=r"(b) : "l"(v));
    lo = __uint_as_float(a); hi = __uint_as_float(b);
}
__device__ __forceinline__ void fma2(ull& d, ull a, ull b) {
    asm("fma.rn.f32x2 %0, %1, %2, %0;" : "+l"(d) : "l"(a), "l"(b));
}

// ---------- dense layer over 2 blocked batches ----------
// in may be smem or global (generic loads). rows [F][NI].
template<int FI, int FO, int WS, int JT, bool RELU, int BMODE>
__device__ __forceinline__ void dense(const float* __restrict__ W,
                                      const void* __restrict__ Bv,
                                      const float* in_sh, float* out_sh) {
    static_assert(FO % JT == 0, "FO divisible by JT");
    constexpr int U = (FO / JT) * 5;
    const int tid = threadIdx.x;
    for (int u = tid; u < U; u += TPB) {
        const int q  = u / 5;
        const int tg = u % 5;
        const int j0 = q * JT;
        float* op0 = out_sh + j0 * NI + 4 * tg;
        ull acc[JT][4];
        #pragma unroll
        for (int j = 0; j < JT; j++) {
            if constexpr (BMODE == 2) {
                const float* op = op0 + j * NI;
                const ulonglong2 p0 = *reinterpret_cast<const ulonglong2*>(op);
                const ulonglong2 p1 = *reinterpret_cast<const ulonglong2*>(op + 20);
                acc[j][0] = p0.x; acc[j][1] = p0.y;
                acc[j][2] = p1.x; acc[j][3] = p1.y;
            } else if constexpr (BMODE == 1) {
                const ull bb = reinterpret_cast<const ull*>(Bv)[j0 + j];
                float blo, bhi; upk2(bb, blo, bhi);
                acc[j][0] = acc[j][1] = pk2(blo, blo);
                acc[j][2] = acc[j][3] = pk2(bhi, bhi);
            } else {
                const float b = reinterpret_cast<const float*>(Bv)[j0 + j];
                const ull bb = pk2(b, b);
                #pragma unroll
                for (int pg = 0; pg < 4; pg++) acc[j][pg] = bb;
            }
        }
        const float* wp = W + j0;
        const float* ip = in_sh + 4 * tg;
        #pragma unroll 4
        for (int i = 0; i < FI; i++) {
            const ulonglong2 v0 = *reinterpret_cast<const ulonglong2*>(ip + i * NI);
            const ulonglong2 v1 = *reinterpret_cast<const ulonglong2*>(ip + i * NI + 20);
            float w[JT];
            if constexpr (JT == 4) {
                const float4 wv = *reinterpret_cast<const float4*>(wp + i * WS);
                w[0] = wv.x; w[1] = wv.y; w[2] = wv.z; w[3] = wv.w;
            } else {
                #pragma unroll
                for (int jj = 0; jj < JT / 2; jj++) {
                    const float2 wv =
                        *reinterpret_cast<const float2*>(wp + i * WS + 2 * jj);
                    w[2 * jj] = wv.x; w[2 * jj + 1] = wv.y;
                }
            }
            #pragma unroll
            for (int j = 0; j < JT; j++) {
                const ull wd = pk2(w[j], w[j]);
                fma2(acc[j][0], v0.x, wd);
                fma2(acc[j][1], v0.y, wd);
                fma2(acc[j][2], v1.x, wd);
                fma2(acc[j][3], v1.y, wd);
            }
        }
        #pragma unroll
        for (int j = 0; j < JT; j++) {
            if (RELU) {
                #pragma unroll
                for (int pg = 0; pg < 4; pg++) {
                    float a, b; upk2(acc[j][pg], a, b);
                    acc[j][pg] = pk2(fmaxf(a, 0.f), fmaxf(b, 0.f));
                }
            }
            ulonglong2 s0, s1;
            s0.x = acc[j][0]; s0.y = acc[j][1];
            s1.x = acc[j][2]; s1.y = acc[j][3];
            float* op = op0 + j * NI;
            *reinterpret_cast<ulonglong2*>(op)      = s0;
            *reinterpret_cast<ulonglong2*>(op + 20) = s1;
        }
    }
}

// ---------- fused pass: out1 = relu(W1.in + b1) [-> global], out2 = relu(W2.in + fold2) ----------
template<int FI, int FO>
__device__ __forceinline__ void dense_fused(const float* __restrict__ W1,
                                            const float* __restrict__ Bv1,
                                            const float* __restrict__ W2,
                                            const ull* __restrict__ fold2,
                                            const float* in_sh,
                                            float* out1, float* out2) {
    constexpr int U = (FO / 4) * 5;
    const int tid = threadIdx.x;
    for (int u = tid; u < U; u += TPB) {
        const int q  = u / 5;
        const int tg = u % 5;
        const int j0 = 4 * q;
        ull a1[4][4], a2[4][4];
        #pragma unroll
        for (int j = 0; j < 4; j++) {
            const float b = Bv1[j0 + j];
            const ull bb = pk2(b, b);
            #pragma unroll
            for (int pg = 0; pg < 4; pg++) a1[j][pg] = bb;
            float lo, hi; upk2(fold2[j0 + j], lo, hi);
            a2[j][0] = a2[j][1] = pk2(lo, lo);
            a2[j][2] = a2[j][3] = pk2(hi, hi);
        }
        const float* ip = in_sh + 4 * tg;
        #pragma unroll 2
        for (int i = 0; i < FI; i++) {
            const ulonglong2 v0 = *reinterpret_cast<const ulonglong2*>(ip + i * NI);
            const ulonglong2 v1 = *reinterpret_cast<const ulonglong2*>(ip + i * NI + 20);
            const float4 w1 = *reinterpret_cast<const float4*>(W1 + i * FO + j0);
            const float4 w2 = *reinterpret_cast<const float4*>(W2 + i * FO + j0);
            const float wa1[4] = {w1.x, w1.y, w1.z, w1.w};
            const float wa2[4] = {w2.x, w2.y, w2.z, w2.w};
            #pragma unroll
            for (int j = 0; j < 4; j++) {
                const ull d1 = pk2(wa1[j], wa1[j]);
                fma2(a1[j][0], v0.x, d1); fma2(a1[j][1], v0.y, d1);
                fma2(a1[j][2], v1.x, d1); fma2(a1[j][3], v1.y, d1);
                const ull d2 = pk2(wa2[j], wa2[j]);
                fma2(a2[j][0], v0.x, d2); fma2(a2[j][1], v0.y, d2);
                fma2(a2[j][2], v1.x, d2); fma2(a2[j][3], v1.y, d2);
            }
        }
        #pragma unroll
        for (int j = 0; j < 4; j++) {
            #pragma unroll
            for (int pg = 0; pg < 4; pg++) {
                float a, b;
                upk2(a1[j][pg], a, b);
                a1[j][pg] = pk2(fmaxf(a, 0.f), fmaxf(b, 0.f));
                upk2(a2[j][pg], a, b);
                a2[j][pg] = pk2(fmaxf(a, 0.f), fmaxf(b, 0.f));
            }
            float* o1 = out1 + (j0 + j) * NI + 4 * tg;
            float* o2 = out2 + (j0 + j) * NI + 4 * tg;
            ulonglong2 s;
            s.x = a1[j][0]; s.y = a1[j][1];
            *reinterpret_cast<ulonglong2*>(o1) = s;
            s.x = a1[j][2]; s.y = a1[j][3];
            *reinterpret_cast<ulonglong2*>(o1 + 20) = s;
            s.x = a2[j][0]; s.y = a2[j][1];
            *reinterpret_cast<ulonglong2*>(o2) = s;
            s.x = a2[j][2]; s.y = a2[j][3];
            *reinterpret_cast<ulonglong2*>(o2 + 20) = s;
        }
    }
}

// ---------- vectorized two-stage fold ----------
template<int F1, int FG, int FO>
__device__ __forceinline__ void fold_bias_v(const float* __restrict__ W,
                                            const float* __restrict__ Bv,
                                            const ull* gv2, ull* fold2,
                                            ull* scratch) {
    constexpr int IC = 5;
    constexpr int CH = FG / IC;
    constexpr int U  = (FO / 4) * IC;
    const int tid = threadIdx.x;
    for (int u = tid; u < U; u += TPB) {
        const int q = u / IC, ic = u % IC;
        const int j0 = 4 * q, i0 = ic * CH;
        ull acc[4] = {0, 0, 0, 0};
        #pragma unroll
        for (int k = 0; k < CH; k++) {
            const int i = i0 + k;
            const float4 wv = *reinterpret_cast<const float4*>(W + (F1 + i) * FO + j0);
            const ull g = gv2[i];
            fma2(acc[0], g, pk2(wv.x, wv.x));
            fma2(acc[1], g, pk2(wv.y, wv.y));
            fma2(acc[2], g, pk2(wv.z, wv.z));
            fma2(acc[3], g, pk2(wv.w, wv.w));
        }
        #pragma unroll
        for (int jj = 0; jj < 4; jj++) scratch[u * 4 + jj] = acc[jj];
    }
    __syncthreads();
    if (tid < FO) {
        const int q = tid / 4, jj = tid % 4;
        const float b = Bv[tid];
        ull acc = pk2(b, b);
        const ull one = pk2(1.f, 1.f);
        #pragma unroll
        for (int ic = 0; ic < IC; ic++)
            fma2(acc, scratch[(q * IC + ic) * 4 + jj], one);
        fold2[tid] = acc;
    }
}

// smem layout (floats): A(100 rows) + B(100 rows) + C(50 rows) + misc = 42.5KB
#define OFF_A    0
#define OFF_B    (OFF_A + 100 * NI)
#define OFF_C    (OFF_B + 100 * NI)
#define OFF_G2   (OFF_C + 50 * NI)      // 100 ull = 200 floats
#define OFF_FOLD (OFF_G2 + 200)         // 100 ull = 200 floats
#define OFF_WS2  (OFF_FOLD + 200)       // 50 ull = 100 floats
#define OFF_MASK (OFF_WS2 + 100)
#define OFF_SE   (OFF_MASK + NI)
#define OFF_W    (OFF_SE + NI)
#define SMEM_FLOATS (OFF_W + NI)
#define SMEM_BYTES (SMEM_FLOATS * 4)

__global__ void __launch_bounds__(TPB, 5)
sp_kernel(const float* __restrict__ state,
          const float* __restrict__ m1w0, const float* __restrict__ m1b0,
          const float* __restrict__ m1w1, const float* __restrict__ m1b1,
          const float* __restrict__ m2w0, const float* __restrict__ m2b0,
          const float* __restrict__ m2w1, const float* __restrict__ m2b1,
          const float* __restrict__ atw0, const float* __restrict__ atb0,
          const float* __restrict__ atw1, const float* __restrict__ atb1,
          const float* __restrict__ atw2, const float* __restrict__ atb2,
          const float* __restrict__ hpw0, const float* __restrict__ hpb0,
          const float* __restrict__ hpw1, const float* __restrict__ hpb1,
          const float* __restrict__ hpw2, const float* __restrict__ hpb2,
          float* __restrict__ out)
{
    extern __shared__ __align__(16) float sm[];
    float* A       = sm + OFF_A;     // h1; at1 out (atH2); hp1 out (hpH2)
    float* B       = sm + OFF_B;     // m1 tb; fold scratch; ath; hp0 out (hpH)
    float* C       = sm + OFF_C;     // x; then h2
    ull*   g2_sh   = reinterpret_cast<ull*>(sm + OFF_G2);
    ull*   fold2   = reinterpret_cast<ull*>(sm + OFF_FOLD);
    ull*   ws2_sh  = reinterpret_cast<ull*>(sm + OFF_WS2);
    float* mask_sh = sm + OFF_MASK;
    float* se_sh   = sm + OFF_SE;
    float* w_sh    = sm + OFF_W;
    ull*   scratchB = reinterpret_cast<ull*>(B);   // fold scratch (B dead then)

    const int tid = threadIdx.x;
    const int b0  = 2 * blockIdx.x;
    float* m2h = g_m2h + (size_t)blockIdx.x * SCRATCH_STRIDE;  // global spill

    // ---- load 2 batches of state: blocked layout [b0 | b1], feature-major, x -> C ----
    const float* st = state + (size_t)b0 * (NTOK * 14);
    for (int t = tid; t < 2 * NTOK * 14; t += TPB) {
        const int bi = t / (NTOK * 14);
        const int r  = t - bi * (NTOK * 14);
        const int n  = r / 14, d = r % 14;
        const float v = st[(size_t)bi * (NTOK * 14) + r];
        if (d == 13) mask_sh[bi * NTOK + n] = v;
        else         C[d * NI + bi * NTOK + n] = v;
    }
    __syncthreads();

    // ---- m1 in 3 chunks of 50: tb = relu(W0 chunk) in B, A += W1 chunk . tb ----
    dense<13, 50, 150, 2, true, 0>(m1w0 +   0, m1b0 +   0, C, B);
    __syncthreads();
    dense<50, 100, 100, 4, false, 0>(m1w1 +    0, m1b1, B, A);
    __syncthreads();
    dense<13, 50, 150, 2, true, 0>(m1w0 +  50, m1b0 +  50, C, B);
    __syncthreads();
    dense<50, 100, 100, 4, false, 2>(m1w1 + 5000, (const void*)0, B, A);
    __syncthreads();
    dense<13, 50, 150, 2, true, 0>(m1w0 + 100, m1b0 + 100, C, B);
    __syncthreads();
    dense<50, 100, 100, 4, true, 2>(m1w1 + 10000, (const void*)0, B, A);
    __syncthreads();
    // A = h1; x (C) dead; B (tb) dead

    // ---- masked mean of h1 -> g2 packed (b0,b1) ----
    if (tid < 100) {
        const ull* mp = reinterpret_cast<const ull*>(mask_sh);
        const ull* hp = reinterpret_cast<const ull*>(A + tid * NI);
        const ull one = pk2(1.f, 1.f);
        float g[2];
        #pragma unroll
        for (int bi = 0; bi < 2; bi++) {
            ull macc = 0, acc = 0;
            #pragma unroll
            for (int k = 0; k < 10; k++) {
                fma2(macc, mp[bi * 10 + k], one);
                fma2(acc,  hp[bi * 10 + k], mp[bi * 10 + k]);
            }
            float a, b; upk2(macc, a, b);
            const float ms = a + b;
            upk2(acc, a, b);
            g[bi] = (ms > 0.f) ? (a + b) * (1.f / ms) : 0.f;
        }
        g2_sh[tid] = pk2(g[0], g[1]);
    }
    __syncthreads();

    // ---- fold at0's global half (scratch in dead B) ----
    fold_bias_v<100, 100, 100>(atw0, atb0, g2_sh, fold2, scratchB);
    __syncthreads();

    // ---- FUSED: m2w0 (A -> global m2h) + at0 (A -> B), one read of h1 ----
    dense_fused<100, 100>(m2w0, m2b0, atw0, fold2, A, m2h, B);
    __syncthreads();
    // A (h1) dead

    // ---- m2w1: global m2h -> h2 in C[0:50]; at1: B (ath) -> A (atH2)
    //      (independent after the fused barrier: different in/out buffers;
    //       back-to-back so m2h global latency overlaps at1's FFMA stream) ----
    dense<100, 50, 50, 2, false, 0>(m2w1, m2b1, m2h, C);
    dense<100, 100, 100, 4, true, 0>(atw1, atb1, B, A);
    __syncthreads();

    // ---- attention scores from A ----
    if (tid < NI) {
        float s = atb2[0];
        #pragma unroll 4
        for (int i = 0; i < 100; i++) s = fmaf(A[i * NI + tid], atw2[i], s);
        s *= mask_sh[tid];
        se_sh[tid] = (s != 0.f) ? expf(s) : 0.f;
    }
    __syncthreads();
    if (tid < NI) {
        const int bi = tid / NTOK;
        float ssum = 0.f;
        #pragma unroll
        for (int n = 0; n < NTOK; n++) ssum += se_sh[bi * NTOK + n];
        w_sh[tid] = (ssum > 0.f) ? se_sh[tid] / ssum : 0.f;
    }
    __syncthreads();

    // ---- weighted sum of h2 (C) -> ws2 packed (b0,b1) ----
    if (tid < 50) {
        const ull* hp = reinterpret_cast<const ull*>(C + tid * NI);
        const ull* wp = reinterpret_cast<const ull*>(w_sh);
        float r[2];
        #pragma unroll
        for (int bi = 0; bi < 2; bi++) {
            ull acc = 0;
            #pragma unroll
            for (int k = 0; k < 10; k++) fma2(acc, hp[bi * 10 + k], wp[bi * 10 + k]);
            float a, b; upk2(acc, a, b);
            r[bi] = a + b;
        }
        ws2_sh[tid] = pk2(r[0], r[1]);
    }
    __syncthreads();

    // ---- fold hp0's weighted-sum half (scratch in dead B: ath consumed) ----
    fold_bias_v<50, 50, 100>(hpw0, hpb0, ws2_sh, fold2, scratchB);
    __syncthreads();

    // ---- head: hp0: C (h2) -> B (fold bias), hp1: B -> A ----
    dense<50, 100, 100, 4, true, 1>(hpw0, fold2, C, B);
    __syncthreads();
    dense<100, 100, 100, 4, true, 0>(hpw1, hpb1, B, A);
    __syncthreads();

    // ---- final 100 -> 7 from A: unit = (batch, token-pair, neuron) = 140 ----
    for (int t = tid; t < 140; t += TPB) {
        const int bi = t / 70;
        const int r  = t % 70;
        const int k  = r / 7, j = r % 7;
        ull acc = pk2(hpb2[j], hpb2[j]);
        const ull* ip = reinterpret_cast<const ull*>(A) + bi * 10 + k;
        #pragma unroll 4
        for (int i = 0; i < 100; i++) {
            const float w = hpw2[i * 7 + j];
            fma2(acc, ip[i * (NI / 2)], pk2(w, w));
        }
        float a, c; upk2(acc, a, c);
        float* ob = out + (size_t)(b0 + bi) * (NTOK * 7);
        ob[(2 * k)     * 7 + j] = a;
        ob[(2 * k + 1) * 7 + j] = c;
    }
}

extern "C" void kernel_launch(void* const* d_in, const int* in_sizes, int n_in,
                              void* d_out, int out_size) {
    cudaFuncSetAttribute(sp_kernel,
                         cudaFuncAttributeMaxDynamicSharedMemorySize, SMEM_BYTES);
    cudaFuncSetAttribute(sp_kernel,
                         cudaFuncAttributePreferredSharedMemoryCarveout, 100);

    // state is the only huge tensor (B*20*14 elems); detect its position by size.
    int si, wb;
    if (in_sizes[0] > 1000000) { si = 0;        wb = 1; }
    else                       { si = n_in - 1; wb = 0; }
    const float* state = (const float*)d_in[si];
    const int B = in_sizes[si] / (NTOK * 14);

    sp_kernel<<<B / 2, TPB, SMEM_BYTES>>>(
        state,
        (const float*)d_in[wb + 0],  (const float*)d_in[wb + 1],
        (const float*)d_in[wb + 2],  (const float*)d_in[wb + 3],
        (const float*)d_in[wb + 4],  (const float*)d_in[wb + 5],
        (const float*)d_in[wb + 6],  (const float*)d_in[wb + 7],
        (const float*)d_in[wb + 8],  (const float*)d_in[wb + 9],
        (const float*)d_in[wb + 10], (const float*)d_in[wb + 11],
        (const float*)d_in[wb + 12], (const float*)d_in[wb + 13],
        (const float*)d_in[wb + 14], (const float*)d_in[wb + 15],
        (const float*)d_in[wb + 16], (const float*)d_in[wb + 17],
        (const float*)d_in[wb + 18], (const float*)d_in[wb + 19],
        (float*)d_out);
}